// round 1
// baseline (speedup 1.0000x reference)
#include <cuda_runtime.h>
#include <cstdint>

// Problem constants
#define BB 4
#define NN 4096
#define DIM 1024
#define HH 16
#define HD 64
#define MM (BB * NN)          // 16384 rows
#define BH (BB * HH)          // 64

// Scratch (allocation-free rule: __device__ globals)
static __device__ float g_q[(size_t)MM * DIM];
static __device__ float g_k[(size_t)MM * DIM];
static __device__ float g_v[(size_t)MM * DIM];
static __device__ float g_ctx[(size_t)MM * DIM];
static __device__ float g_kv[(size_t)BH * HD * HD];     // (b,h,d,p)
static __device__ float g_ksum[(size_t)BH * HD];        // (b,h,d)
static __device__ float g_denom[(size_t)MM * HH];       // (b,n,h)

// ---------------------------------------------------------------------------
// Kernel 0: zero the accumulation buffers (kv, ksum) each launch
// ---------------------------------------------------------------------------
__global__ void zero_acc_kernel() {
    int i = blockIdx.x * 256 + threadIdx.x;
    if (i < BH * HD * HD) g_kv[i] = 0.0f;
    if (i < BH * HD)      g_ksum[i] = 0.0f;
}

// ---------------------------------------------------------------------------
// Kernel 1: QKV projection GEMM.
//   out[m][n] = sum_k x[m][k] * W[n][k] + bias[n]   (+ relu for q,k)
// 128x128 tile, BK=16, 256 threads, 8x8 per thread.
// grid = (DIM/128, MM/128, 3); z selects q/k/v.
// ---------------------------------------------------------------------------
#define GBM 128
#define GBN 128
#define GBK 16

__global__ __launch_bounds__(256, 2)
void qkv_gemm_kernel(const float* __restrict__ x,
                     const float* __restrict__ Wq, const float* __restrict__ bq,
                     const float* __restrict__ Wk, const float* __restrict__ bk,
                     const float* __restrict__ Wv, const float* __restrict__ bv) {
    const float* W;
    const float* bias;
    float* out;
    bool relu;
    if (blockIdx.z == 0)      { W = Wq; bias = bq; out = g_q; relu = true;  }
    else if (blockIdx.z == 1) { W = Wk; bias = bk; out = g_k; relu = true;  }
    else                      { W = Wv; bias = bv; out = g_v; relu = false; }

    __shared__ float As[GBK][GBM + 4];
    __shared__ float Bs[GBK][GBN + 4];

    const int tid = threadIdx.x;
    const int m0 = blockIdx.y * GBM;
    const int n0 = blockIdx.x * GBN;

    const int tx = tid & 15;        // 0..15 -> cols tx*8..+7
    const int ty = tid >> 4;        // 0..15 -> rows ty*8..+7

    // loader mapping: 128 rows x 16 cols per operand; each thread 2 float4
    const int lr = tid >> 2;          // 0..63
    const int lc = (tid & 3) * 4;     // 0,4,8,12

    float acc[8][8];
#pragma unroll
    for (int i = 0; i < 8; i++)
#pragma unroll
        for (int j = 0; j < 8; j++) acc[i][j] = 0.0f;

    for (int k0 = 0; k0 < DIM; k0 += GBK) {
#pragma unroll
        for (int rr = 0; rr < 2; rr++) {
            int row = lr + rr * 64;
            float4 a = *reinterpret_cast<const float4*>(
                &x[(size_t)(m0 + row) * DIM + k0 + lc]);
            As[lc + 0][row] = a.x; As[lc + 1][row] = a.y;
            As[lc + 2][row] = a.z; As[lc + 3][row] = a.w;
            float4 b = *reinterpret_cast<const float4*>(
                &W[(size_t)(n0 + row) * DIM + k0 + lc]);
            Bs[lc + 0][row] = b.x; Bs[lc + 1][row] = b.y;
            Bs[lc + 2][row] = b.z; Bs[lc + 3][row] = b.w;
        }
        __syncthreads();

#pragma unroll
        for (int k = 0; k < GBK; k++) {
            float ra[8], rb[8];
#pragma unroll
            for (int i = 0; i < 8; i++) ra[i] = As[k][ty * 8 + i];
#pragma unroll
            for (int j = 0; j < 8; j++) rb[j] = Bs[k][tx * 8 + j];
#pragma unroll
            for (int i = 0; i < 8; i++)
#pragma unroll
                for (int j = 0; j < 8; j++)
                    acc[i][j] = fmaf(ra[i], rb[j], acc[i][j]);
        }
        __syncthreads();
    }

    float rbias[8];
#pragma unroll
    for (int j = 0; j < 8; j++) rbias[j] = bias[n0 + tx * 8 + j];

#pragma unroll
    for (int i = 0; i < 8; i++) {
        size_t m = (size_t)(m0 + ty * 8 + i);
        float vals[8];
#pragma unroll
        for (int j = 0; j < 8; j++) {
            float v = acc[i][j] + rbias[j];
            vals[j] = relu ? fmaxf(v, 0.0f) : v;
        }
        float4* dst = reinterpret_cast<float4*>(&out[m * DIM + n0 + tx * 8]);
        dst[0] = make_float4(vals[0], vals[1], vals[2], vals[3]);
        dst[1] = make_float4(vals[4], vals[5], vals[6], vals[7]);
    }
}

// ---------------------------------------------------------------------------
// Kernel 2: kv[b,h,d,p] = sum_n k[b,n,h,d] * v[b,n,h,p]; ksum[b,h,d] = sum_n k
// grid = (BH, SPLITS), block 256. Split-K over n with atomicAdd.
// ---------------------------------------------------------------------------
#define KV_SPLITS 8
#define KV_CHUNK 8

__global__ __launch_bounds__(256, 4)
void kv_kernel() {
    const int bh = blockIdx.x;            // 0..63
    const int b = bh >> 4, h = bh & 15;
    const int n_start = blockIdx.y * (NN / KV_SPLITS);
    const int n_end = n_start + (NN / KV_SPLITS);

    __shared__ float ks[KV_CHUNK][HD];
    __shared__ float vs[KV_CHUNK][HD];

    const int tid = threadIdx.x;
    const int tp = (tid & 15) * 4;        // p cols 4
    const int td = (tid >> 4) * 4;        // d rows 4

    float acc[4][4];
#pragma unroll
    for (int i = 0; i < 4; i++)
#pragma unroll
        for (int j = 0; j < 4; j++) acc[i][j] = 0.0f;
    float ksacc = 0.0f;

    const int lrow = tid >> 5;            // 0..7
    const int ld2 = (tid & 31) * 2;       // 0..62

    for (int n = n_start; n < n_end; n += KV_CHUNK) {
        size_t base = ((size_t)(b * NN + n + lrow)) * DIM + h * HD + ld2;
        float2 kk = *reinterpret_cast<const float2*>(&g_k[base]);
        ks[lrow][ld2] = kk.x; ks[lrow][ld2 + 1] = kk.y;
        float2 vv = *reinterpret_cast<const float2*>(&g_v[base]);
        vs[lrow][ld2] = vv.x; vs[lrow][ld2 + 1] = vv.y;
        __syncthreads();

#pragma unroll
        for (int rr = 0; rr < KV_CHUNK; rr++) {
            float kd[4], vp[4];
#pragma unroll
            for (int i = 0; i < 4; i++) { kd[i] = ks[rr][td + i]; vp[i] = vs[rr][tp + i]; }
#pragma unroll
            for (int i = 0; i < 4; i++)
#pragma unroll
                for (int j = 0; j < 4; j++)
                    acc[i][j] = fmaf(kd[i], vp[j], acc[i][j]);
        }
        if (tid < HD) {
#pragma unroll
            for (int rr = 0; rr < KV_CHUNK; rr++) ksacc += ks[rr][tid];
        }
        __syncthreads();
    }

    float* kvout = g_kv + (size_t)bh * HD * HD;
#pragma unroll
    for (int i = 0; i < 4; i++)
#pragma unroll
        for (int j = 0; j < 4; j++)
            atomicAdd(&kvout[(td + i) * HD + tp + j], acc[i][j]);
    if (tid < HD) atomicAdd(&g_ksum[bh * HD + tid], ksacc);
}

// ---------------------------------------------------------------------------
// Kernel 3: ctx[b,n,h,p] = sum_d q[b,n,h,d]*kv[b,h,d,p];
//           denom[b,n,h] = sum_d q[b,n,h,d]*ksum[b,h,d]
// grid = (BH, NN/128), block 256. kv tile cached in smem.
// ---------------------------------------------------------------------------
#define CT_ROWS 128

__global__ __launch_bounds__(256, 2)
void ctx_kernel() {
    const int bh = blockIdx.x;
    const int b = bh >> 4, h = bh & 15;
    const int n0 = blockIdx.y * CT_ROWS;

    __shared__ float kvs[HD][HD + 4];
    __shared__ float ksums[HD];
    __shared__ float qs[CT_ROWS][16 + 1];

    const int tid = threadIdx.x;

    for (int i = tid; i < HD * HD; i += 256)
        kvs[i >> 6][i & 63] = g_kv[(size_t)bh * HD * HD + i];
    if (tid < HD) ksums[tid] = g_ksum[bh * HD + tid];
    __syncthreads();

    const int tx = tid & 15;           // cols tx*4..+3
    const int ty = tid >> 4;           // rows ty*8..+7

    float acc[8][4];
#pragma unroll
    for (int i = 0; i < 8; i++)
#pragma unroll
        for (int j = 0; j < 4; j++) acc[i][j] = 0.0f;
    float dacc[8];
#pragma unroll
    for (int i = 0; i < 8; i++) dacc[i] = 0.0f;

    const int lr = tid >> 1;           // 0..127
    const int lcol = (tid & 1) * 8;    // 0 or 8

    for (int kk = 0; kk < HD; kk += 16) {
        const float* qrow =
            &g_q[((size_t)(b * NN + n0 + lr)) * DIM + h * HD + kk + lcol];
        float4 q1 = *reinterpret_cast<const float4*>(qrow);
        float4 q2 = *reinterpret_cast<const float4*>(qrow + 4);
        qs[lr][lcol + 0] = q1.x; qs[lr][lcol + 1] = q1.y;
        qs[lr][lcol + 2] = q1.z; qs[lr][lcol + 3] = q1.w;
        qs[lr][lcol + 4] = q2.x; qs[lr][lcol + 5] = q2.y;
        qs[lr][lcol + 6] = q2.z; qs[lr][lcol + 7] = q2.w;
        __syncthreads();

#pragma unroll
        for (int k = 0; k < 16; k++) {
            const int kg = kk + k;
            float rkv[4];
#pragma unroll
            for (int j = 0; j < 4; j++) rkv[j] = kvs[kg][tx * 4 + j];
            const float kss = ksums[kg];
#pragma unroll
            for (int i = 0; i < 8; i++) {
                float qv = qs[ty * 8 + i][k];
                dacc[i] = fmaf(qv, kss, dacc[i]);
#pragma unroll
                for (int j = 0; j < 4; j++)
                    acc[i][j] = fmaf(qv, rkv[j], acc[i][j]);
            }
        }
        __syncthreads();
    }

#pragma unroll
    for (int i = 0; i < 8; i++) {
        size_t row = (size_t)(b * NN + n0 + ty * 8 + i);
        float4* dst = reinterpret_cast<float4*>(
            &g_ctx[row * DIM + h * HD + tx * 4]);
        *dst = make_float4(acc[i][0], acc[i][1], acc[i][2], acc[i][3]);
        if (tx == 0) g_denom[row * HH + h] = dacc[i];
    }
}

// ---------------------------------------------------------------------------
// Kernel 4: out = LayerNorm(ctx/denom + x) * gamma + beta
// grid = MM, block 256; 4 elements/thread.
// ---------------------------------------------------------------------------
__device__ __forceinline__ float warp_sum(float v) {
#pragma unroll
    for (int o = 16; o; o >>= 1) v += __shfl_xor_sync(0xffffffffu, v, o);
    return v;
}

__global__ __launch_bounds__(256)
void ln_kernel(const float* __restrict__ x,
               const float* __restrict__ gamma,
               const float* __restrict__ beta,
               float* __restrict__ out) {
    const int row = blockIdx.x;
    const int tid = threadIdx.x;

    __shared__ float den[HH];
    __shared__ float red[8], red2[8];
    __shared__ float s_mu, s_rstd;

    if (tid < HH) den[tid] = fmaxf(g_denom[(size_t)row * HH + tid], 1e-6f);
    __syncthreads();

    float vals[4];
    float s = 0.0f, s2 = 0.0f;
#pragma unroll
    for (int i = 0; i < 4; i++) {
        int j = tid + i * 256;
        float y = g_ctx[(size_t)row * DIM + j] / den[j >> 6]
                  + x[(size_t)row * DIM + j];
        vals[i] = y;
        s += y;
        s2 = fmaf(y, y, s2);
    }
    s = warp_sum(s);
    s2 = warp_sum(s2);
    const int lane = tid & 31, wid = tid >> 5;
    if (lane == 0) { red[wid] = s; red2[wid] = s2; }
    __syncthreads();
    if (wid == 0) {
        float a = (lane < 8) ? red[lane] : 0.0f;
        float b2 = (lane < 8) ? red2[lane] : 0.0f;
        a = warp_sum(a);
        b2 = warp_sum(b2);
        if (lane == 0) {
            float mu = a * (1.0f / DIM);
            float var = b2 * (1.0f / DIM) - mu * mu;
            s_mu = mu;
            s_rstd = rsqrtf(var + 1e-5f);
        }
    }
    __syncthreads();
    const float mu = s_mu, rstd = s_rstd;
#pragma unroll
    for (int i = 0; i < 4; i++) {
        int j = tid + i * 256;
        out[(size_t)row * DIM + j] =
            (vals[i] - mu) * rstd * gamma[j] + beta[j];
    }
}

// ---------------------------------------------------------------------------
// kernel_launch
// inputs: x, Wq, bq, Wk, bk, Wv, bv, gamma, beta
// ---------------------------------------------------------------------------
extern "C" void kernel_launch(void* const* d_in, const int* in_sizes, int n_in,
                              void* d_out, int out_size) {
    const float* x     = (const float*)d_in[0];
    const float* Wq    = (const float*)d_in[1];
    const float* bq    = (const float*)d_in[2];
    const float* Wk    = (const float*)d_in[3];
    const float* bk    = (const float*)d_in[4];
    const float* Wv    = (const float*)d_in[5];
    const float* bv    = (const float*)d_in[6];
    const float* gamma = (const float*)d_in[7];
    const float* beta  = (const float*)d_in[8];
    float* out = (float*)d_out;

    zero_acc_kernel<<<(BH * HD * HD + 255) / 256, 256>>>();

    dim3 ggrid(DIM / GBN, MM / GBM, 3);
    qkv_gemm_kernel<<<ggrid, 256>>>(x, Wq, bq, Wk, bk, Wv, bv);

    kv_kernel<<<dim3(BH, KV_SPLITS), 256>>>();

    ctx_kernel<<<dim3(BH, NN / CT_ROWS), 256>>>();

    ln_kernel<<<MM, 256>>>(x, gamma, beta, out);
}

// round 3
// speedup vs baseline: 2.3132x; 2.3132x over previous
#include <cuda_runtime.h>
#include <cstdint>

// Problem constants
#define BB 4
#define NN 4096
#define DIM 1024
#define HH 16
#define HD 64
#define MM (BB * NN)          // 16384 rows
#define BH (BB * HH)          // 64

// Scratch (allocation-free rule: __device__ globals)
static __device__ float g_q[(size_t)MM * DIM];
static __device__ float g_k[(size_t)MM * DIM];
static __device__ float g_v[(size_t)MM * DIM];
static __device__ float g_ctx[(size_t)MM * DIM];
static __device__ float g_kv[(size_t)BH * HD * HD];     // (b,h,d,p)
static __device__ float g_ksum[(size_t)BH * HD];        // (b,h,d)
static __device__ float g_denom[(size_t)MM * HH];       // (b,n,h)

// ---------------------------------------------------------------------------
// Kernel 0: zero the accumulation buffers (kv, ksum) each launch
// ---------------------------------------------------------------------------
__global__ void zero_acc_kernel() {
    int i = blockIdx.x * 256 + threadIdx.x;
    if (i < BH * HD * HD) g_kv[i] = 0.0f;
    if (i < BH * HD)      g_ksum[i] = 0.0f;
}

// ---------------------------------------------------------------------------
// Kernel 1: QKV projection GEMM on tensor cores (mma.sync m16n8k8 tf32).
//   out[m][n] = sum_k x[m][k] * W[n][k] + bias[n]   (+ relu for q,k)
// Block tile 128x128, BK=16, 256 threads (8 warps, 2m x 4n), warp tile 64x32.
// Inputs rounded to tf32 with cvt.rna (round-to-nearest) during smem staging.
// ---------------------------------------------------------------------------
#define GBM 128
#define GBN 128
#define GBK 16
#define SSTR 20   // smem row stride in floats: (20*m + k) % 32 bijective -> conflict-free

__device__ __forceinline__ unsigned tf32_rna(float x) {
    unsigned u;
    asm("cvt.rna.tf32.f32 %0, %1;" : "=r"(u) : "f"(x));
    return u;
}

__device__ __forceinline__ void mma_tf32(float& d0, float& d1, float& d2, float& d3,
                                         unsigned a0, unsigned a1, unsigned a2, unsigned a3,
                                         unsigned b0, unsigned b1) {
    asm volatile(
        "mma.sync.aligned.m16n8k8.row.col.f32.tf32.tf32.f32 "
        "{%0,%1,%2,%3}, {%4,%5,%6,%7}, {%8,%9}, {%0,%1,%2,%3};"
        : "+f"(d0), "+f"(d1), "+f"(d2), "+f"(d3)
        : "r"(a0), "r"(a1), "r"(a2), "r"(a3), "r"(b0), "r"(b1));
}

__global__ __launch_bounds__(256, 2)
void qkv_gemm_kernel(const float* __restrict__ x,
                     const float* __restrict__ Wq, const float* __restrict__ bq,
                     const float* __restrict__ Wk, const float* __restrict__ bk,
                     const float* __restrict__ Wv, const float* __restrict__ bv) {
    const float* W;
    const float* bias;
    float* out;
    bool relu;
    if (blockIdx.z == 0)      { W = Wq; bias = bq; out = g_q; relu = true;  }
    else if (blockIdx.z == 1) { W = Wk; bias = bk; out = g_k; relu = true;  }
    else                      { W = Wv; bias = bv; out = g_v; relu = false; }

    // A tile: As[m][k] (m=0..127, k=0..15), stride SSTR; same for B (W rows)
    __shared__ unsigned As[2][GBM * SSTR];
    __shared__ unsigned Bs[2][GBM * SSTR];

    const int tid = threadIdx.x;
    const int m0 = blockIdx.y * GBM;
    const int n0 = blockIdx.x * GBN;

    // loader mapping: each thread 2 rows per operand, 4 k's per row
    const int lr = tid >> 2;          // 0..63
    const int lc = (tid & 3) * 4;     // 0,4,8,12

    // warp tiling: 8 warps as 2(m) x 4(n)
    const int w = tid >> 5;
    const int lane = tid & 31;
    const int warp_m = (w & 1) * 64;
    const int warp_n = (w >> 1) * 32;
    const int lq = lane >> 2;         // 0..7
    const int lr4 = lane & 3;         // 0..3

    float acc[4][4][4];
#pragma unroll
    for (int mt = 0; mt < 4; mt++)
#pragma unroll
        for (int nt = 0; nt < 4; nt++)
#pragma unroll
            for (int r = 0; r < 4; r++) acc[mt][nt][r] = 0.0f;

    float4 ax[2], bx[2];

    // prologue: load + stage chunk 0
#pragma unroll
    for (int rr = 0; rr < 2; rr++) {
        int row = lr + rr * 64;
        ax[rr] = *reinterpret_cast<const float4*>(&x[(size_t)(m0 + row) * DIM + lc]);
        bx[rr] = *reinterpret_cast<const float4*>(&W[(size_t)(n0 + row) * DIM + lc]);
    }
#pragma unroll
    for (int rr = 0; rr < 2; rr++) {
        int row = lr + rr * 64;
        unsigned* pa = &As[0][row * SSTR + lc];
        pa[0] = tf32_rna(ax[rr].x); pa[1] = tf32_rna(ax[rr].y);
        pa[2] = tf32_rna(ax[rr].z); pa[3] = tf32_rna(ax[rr].w);
        unsigned* pb = &Bs[0][row * SSTR + lc];
        pb[0] = tf32_rna(bx[rr].x); pb[1] = tf32_rna(bx[rr].y);
        pb[2] = tf32_rna(bx[rr].z); pb[3] = tf32_rna(bx[rr].w);
    }
    __syncthreads();

    const int NCHUNK = DIM / GBK;   // 64
    for (int c = 0; c < NCHUNK; c++) {
        const int buf = c & 1;
        const int nbuf = buf ^ 1;

        // prefetch next chunk from gmem
        if (c + 1 < NCHUNK) {
            int k0 = (c + 1) * GBK;
#pragma unroll
            for (int rr = 0; rr < 2; rr++) {
                int row = lr + rr * 64;
                ax[rr] = *reinterpret_cast<const float4*>(&x[(size_t)(m0 + row) * DIM + k0 + lc]);
                bx[rr] = *reinterpret_cast<const float4*>(&W[(size_t)(n0 + row) * DIM + k0 + lc]);
            }
        }

        // compute on current buffer: 2 k-steps of 8
#pragma unroll
        for (int ks = 0; ks < GBK; ks += 8) {
            unsigned af[4][4];
#pragma unroll
            for (int mt = 0; mt < 4; mt++) {
                int row = warp_m + mt * 16 + lq;
                af[mt][0] = As[buf][row * SSTR + ks + lr4];
                af[mt][1] = As[buf][(row + 8) * SSTR + ks + lr4];
                af[mt][2] = As[buf][row * SSTR + ks + lr4 + 4];
                af[mt][3] = As[buf][(row + 8) * SSTR + ks + lr4 + 4];
            }
            unsigned bf[4][2];
#pragma unroll
            for (int nt = 0; nt < 4; nt++) {
                int nrow = warp_n + nt * 8 + lq;
                bf[nt][0] = Bs[buf][nrow * SSTR + ks + lr4];
                bf[nt][1] = Bs[buf][nrow * SSTR + ks + lr4 + 4];
            }
#pragma unroll
            for (int mt = 0; mt < 4; mt++)
#pragma unroll
                for (int nt = 0; nt < 4; nt++)
                    mma_tf32(acc[mt][nt][0], acc[mt][nt][1], acc[mt][nt][2], acc[mt][nt][3],
                             af[mt][0], af[mt][1], af[mt][2], af[mt][3],
                             bf[nt][0], bf[nt][1]);
        }

        // stage next chunk into the other buffer
        if (c + 1 < NCHUNK) {
#pragma unroll
            for (int rr = 0; rr < 2; rr++) {
                int row = lr + rr * 64;
                unsigned* pa = &As[nbuf][row * SSTR + lc];
                pa[0] = tf32_rna(ax[rr].x); pa[1] = tf32_rna(ax[rr].y);
                pa[2] = tf32_rna(ax[rr].z); pa[3] = tf32_rna(ax[rr].w);
                unsigned* pb = &Bs[nbuf][row * SSTR + lc];
                pb[0] = tf32_rna(bx[rr].x); pb[1] = tf32_rna(bx[rr].y);
                pb[2] = tf32_rna(bx[rr].z); pb[3] = tf32_rna(bx[rr].w);
            }
        }
        __syncthreads();
    }

    // epilogue: bias (+ relu), write as float2 pairs (c-frag col pairs)
#pragma unroll
    for (int nt = 0; nt < 4; nt++) {
        const int col = n0 + warp_n + nt * 8 + lr4 * 2;
        const float b0 = bias[col];
        const float b1 = bias[col + 1];
#pragma unroll
        for (int mt = 0; mt < 4; mt++) {
            const int row = m0 + warp_m + mt * 16 + lq;
            float v0 = acc[mt][nt][0] + b0;
            float v1 = acc[mt][nt][1] + b1;
            float v2 = acc[mt][nt][2] + b0;
            float v3 = acc[mt][nt][3] + b1;
            if (relu) {
                v0 = fmaxf(v0, 0.0f); v1 = fmaxf(v1, 0.0f);
                v2 = fmaxf(v2, 0.0f); v3 = fmaxf(v3, 0.0f);
            }
            *reinterpret_cast<float2*>(&out[(size_t)row * DIM + col]) = make_float2(v0, v1);
            *reinterpret_cast<float2*>(&out[(size_t)(row + 8) * DIM + col]) = make_float2(v2, v3);
        }
    }
}

// ---------------------------------------------------------------------------
// Kernel 2: kv[b,h,d,p] = sum_n k[b,n,h,d] * v[b,n,h,p]; ksum[b,h,d] = sum_n k
// grid = (BH, SPLITS), block 256. Split-K over n with atomicAdd.
// ---------------------------------------------------------------------------
#define KV_SPLITS 8
#define KV_CHUNK 8

__global__ __launch_bounds__(256, 4)
void kv_kernel() {
    const int bh = blockIdx.x;            // 0..63
    const int b = bh >> 4, h = bh & 15;
    const int n_start = blockIdx.y * (NN / KV_SPLITS);
    const int n_end = n_start + (NN / KV_SPLITS);

    __shared__ float ks[KV_CHUNK][HD];
    __shared__ float vs[KV_CHUNK][HD];

    const int tid = threadIdx.x;
    const int tp = (tid & 15) * 4;        // p cols 4
    const int td = (tid >> 4) * 4;        // d rows 4

    float acc[4][4];
#pragma unroll
    for (int i = 0; i < 4; i++)
#pragma unroll
        for (int j = 0; j < 4; j++) acc[i][j] = 0.0f;
    float ksacc = 0.0f;

    const int lrow = tid >> 5;            // 0..7
    const int ld2 = (tid & 31) * 2;       // 0..62

    for (int n = n_start; n < n_end; n += KV_CHUNK) {
        size_t base = ((size_t)(b * NN + n + lrow)) * DIM + h * HD + ld2;
        float2 kk = *reinterpret_cast<const float2*>(&g_k[base]);
        ks[lrow][ld2] = kk.x; ks[lrow][ld2 + 1] = kk.y;
        float2 vv = *reinterpret_cast<const float2*>(&g_v[base]);
        vs[lrow][ld2] = vv.x; vs[lrow][ld2 + 1] = vv.y;
        __syncthreads();

#pragma unroll
        for (int rr = 0; rr < KV_CHUNK; rr++) {
            float kd[4], vp[4];
#pragma unroll
            for (int i = 0; i < 4; i++) { kd[i] = ks[rr][td + i]; vp[i] = vs[rr][tp + i]; }
#pragma unroll
            for (int i = 0; i < 4; i++)
#pragma unroll
                for (int j = 0; j < 4; j++)
                    acc[i][j] = fmaf(kd[i], vp[j], acc[i][j]);
        }
        if (tid < HD) {
#pragma unroll
            for (int rr = 0; rr < KV_CHUNK; rr++) ksacc += ks[rr][tid];
        }
        __syncthreads();
    }

    float* kvout = g_kv + (size_t)bh * HD * HD;
#pragma unroll
    for (int i = 0; i < 4; i++)
#pragma unroll
        for (int j = 0; j < 4; j++)
            atomicAdd(&kvout[(td + i) * HD + tp + j], acc[i][j]);
    if (tid < HD) atomicAdd(&g_ksum[bh * HD + tid], ksacc);
}

// ---------------------------------------------------------------------------
// Kernel 3: ctx[b,n,h,p] = sum_d q[b,n,h,d]*kv[b,h,d,p];
//           denom[b,n,h] = sum_d q[b,n,h,d]*ksum[b,h,d]
// grid = (BH, NN/128), block 256. kv tile cached in smem.
// ---------------------------------------------------------------------------
#define CT_ROWS 128

__global__ __launch_bounds__(256, 2)
void ctx_kernel() {
    const int bh = blockIdx.x;
    const int b = bh >> 4, h = bh & 15;
    const int n0 = blockIdx.y * CT_ROWS;

    __shared__ float kvs[HD][HD + 4];
    __shared__ float ksums[HD];
    __shared__ float qs[CT_ROWS][16 + 1];

    const int tid = threadIdx.x;

    for (int i = tid; i < HD * HD; i += 256)
        kvs[i >> 6][i & 63] = g_kv[(size_t)bh * HD * HD + i];
    if (tid < HD) ksums[tid] = g_ksum[bh * HD + tid];
    __syncthreads();

    const int tx = tid & 15;           // cols tx*4..+3
    const int ty = tid >> 4;           // rows ty*8..+7

    float acc[8][4];
#pragma unroll
    for (int i = 0; i < 8; i++)
#pragma unroll
        for (int j = 0; j < 4; j++) acc[i][j] = 0.0f;
    float dacc[8];
#pragma unroll
    for (int i = 0; i < 8; i++) dacc[i] = 0.0f;

    const int lr = tid >> 1;           // 0..127
    const int lcol = (tid & 1) * 8;    // 0 or 8

    for (int kk = 0; kk < HD; kk += 16) {
        const float* qrow =
            &g_q[((size_t)(b * NN + n0 + lr)) * DIM + h * HD + kk + lcol];
        float4 q1 = *reinterpret_cast<const float4*>(qrow);
        float4 q2 = *reinterpret_cast<const float4*>(qrow + 4);
        qs[lr][lcol + 0] = q1.x; qs[lr][lcol + 1] = q1.y;
        qs[lr][lcol + 2] = q1.z; qs[lr][lcol + 3] = q1.w;
        qs[lr][lcol + 4] = q2.x; qs[lr][lcol + 5] = q2.y;
        qs[lr][lcol + 6] = q2.z; qs[lr][lcol + 7] = q2.w;
        __syncthreads();

#pragma unroll
        for (int k = 0; k < 16; k++) {
            const int kg = kk + k;
            float rkv[4];
#pragma unroll
            for (int j = 0; j < 4; j++) rkv[j] = kvs[kg][tx * 4 + j];
            const float kss = ksums[kg];
#pragma unroll
            for (int i = 0; i < 8; i++) {
                float qv = qs[ty * 8 + i][k];
                dacc[i] = fmaf(qv, kss, dacc[i]);
#pragma unroll
                for (int j = 0; j < 4; j++)
                    acc[i][j] = fmaf(qv, rkv[j], acc[i][j]);
            }
        }
        __syncthreads();
    }

#pragma unroll
    for (int i = 0; i < 8; i++) {
        size_t row = (size_t)(b * NN + n0 + ty * 8 + i);
        float4* dst = reinterpret_cast<float4*>(
            &g_ctx[row * DIM + h * HD + tx * 4]);
        *dst = make_float4(acc[i][0], acc[i][1], acc[i][2], acc[i][3]);
        if (tx == 0) g_denom[row * HH + h] = dacc[i];
    }
}

// ---------------------------------------------------------------------------
// Kernel 4: out = LayerNorm(ctx/denom + x) * gamma + beta
// grid = MM, block 256; 4 elements/thread.
// ---------------------------------------------------------------------------
__device__ __forceinline__ float warp_sum(float v) {
#pragma unroll
    for (int o = 16; o; o >>= 1) v += __shfl_xor_sync(0xffffffffu, v, o);
    return v;
}

__global__ __launch_bounds__(256)
void ln_kernel(const float* __restrict__ x,
               const float* __restrict__ gamma,
               const float* __restrict__ beta,
               float* __restrict__ out) {
    const int row = blockIdx.x;
    const int tid = threadIdx.x;

    __shared__ float den[HH];
    __shared__ float red[8], red2[8];
    __shared__ float s_mu, s_rstd;

    if (tid < HH) den[tid] = fmaxf(g_denom[(size_t)row * HH + tid], 1e-6f);
    __syncthreads();

    float vals[4];
    float s = 0.0f, s2 = 0.0f;
#pragma unroll
    for (int i = 0; i < 4; i++) {
        int j = tid + i * 256;
        float y = g_ctx[(size_t)row * DIM + j] / den[j >> 6]
                  + x[(size_t)row * DIM + j];
        vals[i] = y;
        s += y;
        s2 = fmaf(y, y, s2);
    }
    s = warp_sum(s);
    s2 = warp_sum(s2);
    const int lane = tid & 31, wid = tid >> 5;
    if (lane == 0) { red[wid] = s; red2[wid] = s2; }
    __syncthreads();
    if (wid == 0) {
        float a = (lane < 8) ? red[lane] : 0.0f;
        float b2 = (lane < 8) ? red2[lane] : 0.0f;
        a = warp_sum(a);
        b2 = warp_sum(b2);
        if (lane == 0) {
            float mu = a * (1.0f / DIM);
            float var = b2 * (1.0f / DIM) - mu * mu;
            s_mu = mu;
            s_rstd = rsqrtf(var + 1e-5f);
        }
    }
    __syncthreads();
    const float mu = s_mu, rstd = s_rstd;
#pragma unroll
    for (int i = 0; i < 4; i++) {
        int j = tid + i * 256;
        out[(size_t)row * DIM + j] =
            (vals[i] - mu) * rstd * gamma[j] + beta[j];
    }
}

// ---------------------------------------------------------------------------
// kernel_launch
// inputs: x, Wq, bq, Wk, bk, Wv, bv, gamma, beta
// ---------------------------------------------------------------------------
extern "C" void kernel_launch(void* const* d_in, const int* in_sizes, int n_in,
                              void* d_out, int out_size) {
    const float* x     = (const float*)d_in[0];
    const float* Wq    = (const float*)d_in[1];
    const float* bq    = (const float*)d_in[2];
    const float* Wk    = (const float*)d_in[3];
    const float* bk    = (const float*)d_in[4];
    const float* Wv    = (const float*)d_in[5];
    const float* bv    = (const float*)d_in[6];
    const float* gamma = (const float*)d_in[7];
    const float* beta  = (const float*)d_in[8];
    float* out = (float*)d_out;

    zero_acc_kernel<<<(BH * HD * HD + 255) / 256, 256>>>();

    dim3 ggrid(DIM / GBN, MM / GBM, 3);
    qkv_gemm_kernel<<<ggrid, 256>>>(x, Wq, bq, Wk, bk, Wv, bv);

    kv_kernel<<<dim3(BH, KV_SPLITS), 256>>>();

    ctx_kernel<<<dim3(BH, NN / CT_ROWS), 256>>>();

    ln_kernel<<<MM, 256>>>(x, gamma, beta, out);
}